// round 1
// baseline (speedup 1.0000x reference)
#include <cuda_runtime.h>

// TorchWrithe: writhe of all non-adjacent segment pairs per frame.
// B=128 frames, N=300 atoms, SEG_LEN=1 -> S=44253 pairs, out (B,S) f32.
//
// Segment row s corresponds to (i, j): i ascending, j in [i+2, 298] ascending
// (np.triu_indices(299,k=1) row-major, adjacent pairs j==i+1 filtered out).
// cum(i) = 297*i - i*(i-1)/2 rows precede block i.

#define N_FRAMES_C 128
#define N_ATOMS_C  300
#define S_PAIRS_C  44253
#define FLOATS_PER_FRAME (N_ATOMS_C * 3)
#define BLOCK_T 256

__device__ __forceinline__ int fcum(int i) {
    return 297 * i - (i * (i - 1)) / 2;
}

struct V3 { float x, y, z; };

__device__ __forceinline__ V3 vsub(V3 a, V3 b) { return {a.x-b.x, a.y-b.y, a.z-b.z}; }
__device__ __forceinline__ V3 vcross(V3 a, V3 b) {
    return { a.y*b.z - a.z*b.y,
             a.z*b.x - a.x*b.z,
             a.x*b.y - a.y*b.x };
}
__device__ __forceinline__ float vdot(V3 a, V3 b) {
    return fmaf(a.x, b.x, fmaf(a.y, b.y, a.z * b.z));
}

__global__ __launch_bounds__(BLOCK_T)
void writhe_kernel(const float* __restrict__ xyz, float* __restrict__ out) {
    __shared__ float sm[FLOATS_PER_FRAME];
    const int b = blockIdx.y;
    const float* fr = xyz + b * FLOATS_PER_FRAME;
    for (int t = threadIdx.x; t < FLOATS_PER_FRAME; t += BLOCK_T)
        sm[t] = fr[t];
    __syncthreads();

    const int s = blockIdx.x * BLOCK_T + threadIdx.x;
    if (s >= S_PAIRS_C) return;

    // Invert s -> (i, j). Solve i^2 - 595 i + 2 s = 0, fix up with +-1 steps.
    float disc = 354025.0f - 8.0f * (float)s;
    int i = (int)((595.0f - sqrtf(disc)) * 0.5f);
    if (i < 0) i = 0;
    if (i > 296) i = 296;
    while (i > 0 && fcum(i) > s) --i;
    while (fcum(i + 1) <= s) ++i;
    const int j = i + 2 + (s - fcum(i));

    // Atom coordinates from shared memory.
    const float* a0 = &sm[3 * i];
    const float* a2 = &sm[3 * j];
    V3 p0 = { a0[0], a0[1], a0[2] };
    V3 p1 = { a0[3], a0[4], a0[5] };
    V3 p2 = { a2[0], a2[1], a2[2] };
    V3 p3 = { a2[3], a2[4], a2[5] };

    // Unnormalized direction vectors (normalization is redundant: the crosses
    // are normalized below and the sign term is scale-invariant).
    V3 v0 = vsub(p2, p0);
    V3 v1 = vsub(p2, p1);
    V3 v2 = vsub(p3, p0);
    V3 v3 = vsub(p3, p1);

    // crosses per reference permutation: c0=d0xd1, c1=d1xd3, c2=d3xd2, c3=d2xd0
    V3 c0 = vcross(v0, v1);
    V3 c1 = vcross(v1, v3);
    V3 c2 = vcross(v3, v2);
    V3 c3 = vcross(v2, v0);

    float n0 = vdot(c0, c0);
    float n1 = vdot(c1, c1);
    float n2 = vdot(c2, c2);
    float n3 = vdot(c3, c3);

    // dot(unit(ca), unit(cb)) = dot(ca,cb) * rsqrt(|ca|^2 * |cb|^2)
    float t0 = vdot(c0, c1) * rsqrtf(n0 * n1);
    float t1 = vdot(c1, c2) * rsqrtf(n1 * n2);
    float t2 = vdot(c2, c3) * rsqrtf(n2 * n3);
    float t3 = vdot(c3, c0) * rsqrtf(n3 * n0);

    t0 = fminf(fmaxf(t0, -1.0f), 1.0f);
    t1 = fminf(fmaxf(t1, -1.0f), 1.0f);
    t2 = fminf(fmaxf(t2, -1.0f), 1.0f);
    t3 = fminf(fmaxf(t3, -1.0f), 1.0f);

    float omega = asinf(t0) + asinf(t1) + asinf(t2) + asinf(t3);

    // sign(dot(cross(p3-p2, p1-p0), v0)); scale-invariant so v0 unnormalized ok.
    V3 u = vsub(p3, p2);
    V3 w = vsub(p1, p0);
    float sg = vdot(vcross(u, w), v0);
    float sign = (sg > 0.0f) ? 1.0f : ((sg < 0.0f) ? -1.0f : 0.0f);

    out[b * S_PAIRS_C + s] = omega * sign * 0.15915494309189535f; // 1/(2*pi)
}

extern "C" void kernel_launch(void* const* d_in, const int* in_sizes, int n_in,
                              void* d_out, int out_size) {
    const float* xyz = (const float*)d_in[0];
    float* out = (float*)d_out;
    dim3 grid((S_PAIRS_C + BLOCK_T - 1) / BLOCK_T, N_FRAMES_C);
    writhe_kernel<<<grid, BLOCK_T>>>(xyz, out);
}

// round 4
// speedup vs baseline: 1.2598x; 1.2598x over previous
#include <cuda_runtime.h>

// TorchWrithe: writhe of all non-adjacent segment pairs per frame.
// B=128, N=300, SEG_LEN=1 -> S=44253 pairs, out (B,S) f32.
// Segment row s <-> (i, j): i ascending, j in [i+2, 298]; cum(i)=297i - i(i-1)/2.

#define N_FRAMES_C 128
#define N_ATOMS_C  300
#define S_PAIRS_C  44253
#define BLOCK_T 256
#define F_TILE 8
#define FLOATS_PER_FRAME (N_ATOMS_C * 3)

__device__ __forceinline__ int fcum(int i) {
    return 297 * i - (i * (i - 1)) / 2;
}

struct V3 { float x, y, z; };

__device__ __forceinline__ V3 vsub(V3 a, V3 b) { return {a.x-b.x, a.y-b.y, a.z-b.z}; }
__device__ __forceinline__ V3 vcross(V3 a, V3 b) {
    return { a.y*b.z - a.z*b.y,
             a.z*b.x - a.x*b.z,
             a.x*b.y - a.y*b.x };
}
__device__ __forceinline__ float vdot(V3 a, V3 b) {
    return fmaf(a.x, b.x, fmaf(a.y, b.y, a.z * b.z));
}

// Branchless asinf (cephes poly). Inputs may be slightly outside [-1,1] due to
// rounding: then z=(1-|x|)/2 < 0, fmaxf clamps it to 0 -> result = +-pi/2 (the
// clamped-asin answer). So no explicit clamp needed by the caller.
__device__ __forceinline__ float fast_asinf(float x) {
    float a = fabsf(x);
    bool big = a > 0.5f;
    float z = big ? fmaxf(fmaf(a, -0.5f, 0.5f), 0.0f) : a * a;
    // sqrt(z) = z * rsqrt(z); guard z==0 (a==1) -> zs ~ 0, correct.
    float zs = z * rsqrtf(fmaxf(z, 1e-30f));
    float sv = big ? zs : a;
    float p =           4.2163199048e-2f;
    p = fmaf(p, z,      2.4181311049e-2f);
    p = fmaf(p, z,      4.5470025998e-2f);
    p = fmaf(p, z,      7.4953002686e-2f);
    p = fmaf(p, z,      1.6666752422e-1f);
    float r = fmaf(sv * z, p, sv);                       // asin(sv)
    float res = big ? fmaf(-2.0f, r, 1.5707963267948966f) : r;
    return copysignf(res, x);
}

__global__ __launch_bounds__(BLOCK_T)
void writhe_kernel(const float* __restrict__ xyz, float* __restrict__ out) {
    __shared__ float4 sm[F_TILE][N_ATOMS_C];   // padded atoms, 38400 B

    const int b0 = blockIdx.y * F_TILE;
    const float* __restrict__ src = xyz + (size_t)b0 * FLOATS_PER_FRAME;
    for (int idx = threadIdx.x; idx < F_TILE * FLOATS_PER_FRAME; idx += BLOCK_T) {
        int f = idx / FLOATS_PER_FRAME;
        int r = idx - f * FLOATS_PER_FRAME;
        int a = r / 3;
        int c = r - 3 * a;
        ((float*)&sm[f][a])[c] = src[idx];
    }
    __syncthreads();

    const int s = blockIdx.x * BLOCK_T + threadIdx.x;
    if (s >= S_PAIRS_C) return;

    // Invert s -> (i, j), once per thread (amortized over F_TILE frames).
    float disc = 354025.0f - 8.0f * (float)s;
    int i = (int)((595.0f - sqrtf(disc)) * 0.5f);
    if (i < 0) i = 0;
    if (i > 296) i = 296;
    while (i > 0 && fcum(i) > s) --i;
    while (fcum(i + 1) <= s) ++i;
    const int j = i + 2 + (s - fcum(i));

    float* __restrict__ op = out + (size_t)b0 * S_PAIRS_C + s;

    #pragma unroll
    for (int f = 0; f < F_TILE; ++f) {
        float4 q0 = sm[f][i];
        float4 q1 = sm[f][i + 1];
        float4 q2 = sm[f][j];
        float4 q3 = sm[f][j + 1];
        V3 p0 = { q0.x, q0.y, q0.z };
        V3 p1 = { q1.x, q1.y, q1.z };
        V3 p2 = { q2.x, q2.y, q2.z };
        V3 p3 = { q3.x, q3.y, q3.z };

        // Unnormalized directions (normalization cancels everywhere).
        V3 v0 = vsub(p2, p0);
        V3 v1 = vsub(p2, p1);
        V3 v2 = vsub(p3, p0);
        V3 v3 = vsub(p3, p1);

        // crosses per reference permutation
        V3 c0 = vcross(v0, v1);
        V3 c1 = vcross(v1, v3);
        V3 c2 = vcross(v3, v2);
        V3 c3 = vcross(v2, v0);

        float n0 = vdot(c0, c0);
        float n1 = vdot(c1, c1);
        float n2 = vdot(c2, c2);
        float n3 = vdot(c3, c3);

        float t0 = vdot(c0, c1) * rsqrtf(n0 * n1);
        float t1 = vdot(c1, c2) * rsqrtf(n1 * n2);
        float t2 = vdot(c2, c3) * rsqrtf(n2 * n3);
        float t3 = vdot(c3, c0) * rsqrtf(n3 * n0);

        float omega = fast_asinf(t0) + fast_asinf(t1)
                    + fast_asinf(t2) + fast_asinf(t3);

        // sign(dot(cross(p3-p2, p1-p0), v0)) == sign(dot(c0, v2))
        float sg = vdot(c0, v2);
        float sign = (sg > 0.0f) ? 1.0f : ((sg < 0.0f) ? -1.0f : 0.0f);

        op[(size_t)f * S_PAIRS_C] = omega * sign * 0.15915494309189535f;
    }
}

extern "C" void kernel_launch(void* const* d_in, const int* in_sizes, int n_in,
                              void* d_out, int out_size) {
    const float* xyz = (const float*)d_in[0];
    float* out = (float*)d_out;
    dim3 grid((S_PAIRS_C + BLOCK_T - 1) / BLOCK_T, N_FRAMES_C / F_TILE);
    writhe_kernel<<<grid, BLOCK_T>>>(xyz, out);
}

// round 5
// speedup vs baseline: 1.6928x; 1.3437x over previous
#include <cuda_runtime.h>

// TorchWrithe: writhe of all non-adjacent segment pairs per frame.
// B=128, N=300, SEG_LEN=1 -> S=44253 pairs, out (B,S) f32.
// Segment row s <-> (i, j): i ascending, j in [i+2, 298]; cum(i)=297i - i(i-1)/2.

#define N_FRAMES_C 128
#define N_ATOMS_C  300
#define S_PAIRS_C  44253
#define BLOCK_T 256
#define F_TILE 8
#define FLOATS_PER_FRAME (N_ATOMS_C * 3)          // 900
#define SLAB_FLOATS (F_TILE * FLOATS_PER_FRAME)   // 7200
#define SLAB_VEC4 (SLAB_FLOATS / 4)               // 1800

__device__ __forceinline__ int fcum(int i) {
    return 297 * i - (i * (i - 1)) / 2;
}

struct V3 { float x, y, z; };

__device__ __forceinline__ V3 vsub(V3 a, V3 b) { return {a.x-b.x, a.y-b.y, a.z-b.z}; }
__device__ __forceinline__ V3 vcross(V3 a, V3 b) {
    return { a.y*b.z - a.z*b.y,
             a.z*b.x - a.x*b.z,
             a.x*b.y - a.y*b.x };
}
__device__ __forceinline__ float vdot(V3 a, V3 b) {
    return fmaf(a.x, b.x, fmaf(a.y, b.y, a.z * b.z));
}

// Branchless asinf (cephes poly). Inputs slightly outside [-1,1] from rounding
// hit the fmaxf(...,0) clamp -> result = +-pi/2 (the clamped-asin answer).
__device__ __forceinline__ float fast_asinf(float x) {
    float a = fabsf(x);
    bool big = a > 0.5f;
    float z = big ? fmaxf(fmaf(a, -0.5f, 0.5f), 0.0f) : a * a;
    float zs = z * rsqrtf(fmaxf(z, 1e-30f));   // sqrt(z), 0-safe
    float sv = big ? zs : a;
    float p =           4.2163199048e-2f;
    p = fmaf(p, z,      2.4181311049e-2f);
    p = fmaf(p, z,      4.5470025998e-2f);
    p = fmaf(p, z,      7.4953002686e-2f);
    p = fmaf(p, z,      1.6666752422e-1f);
    float r = fmaf(sv * z, p, sv);                       // asin(sv)
    float res = big ? fmaf(-2.0f, r, 1.5707963267948966f) : r;
    return copysignf(res, x);
}

__global__ __launch_bounds__(BLOCK_T, 5)
void writhe_kernel(const float* __restrict__ xyz, float* __restrict__ out) {
    // Unpadded linear slab: 8 contiguous frames, float4 memcpy fill (no div/mod).
    __shared__ float sm[SLAB_FLOATS];            // 28800 B

    const int b0 = blockIdx.y * F_TILE;
    {
        const float4* __restrict__ src4 =
            (const float4*)(xyz + (size_t)b0 * FLOATS_PER_FRAME);
        float4* dst4 = (float4*)sm;
        #pragma unroll
        for (int k = 0; k < 8; ++k) {
            int t = threadIdx.x + k * BLOCK_T;
            if (t < SLAB_VEC4) dst4[t] = src4[t];
        }
    }
    __syncthreads();

    const int s = blockIdx.x * BLOCK_T + threadIdx.x;
    if (s >= S_PAIRS_C) return;

    // Invert s -> (i, j), once per thread (amortized over F_TILE frames).
    float disc = 354025.0f - 8.0f * (float)s;
    int i = (int)((595.0f - sqrtf(disc)) * 0.5f);
    if (i < 0) i = 0;
    if (i > 296) i = 296;
    while (i > 0 && fcum(i) > s) --i;
    while (fcum(i + 1) <= s) ++i;
    const int j = i + 2 + (s - fcum(i));

    // Two dynamic shared bases; everything else is immediate offsets.
    const float* __restrict__ bi = sm + 3 * i;   // atoms i, i+1
    const float* __restrict__ bj = sm + 3 * j;   // atoms j, j+1

    float* __restrict__ op = out + (size_t)b0 * S_PAIRS_C + s;

    #pragma unroll
    for (int f = 0; f < F_TILE; ++f) {
        const float* ai = bi + f * FLOATS_PER_FRAME;
        const float* aj = bj + f * FLOATS_PER_FRAME;
        V3 p0 = { ai[0], ai[1], ai[2] };
        V3 p1 = { ai[3], ai[4], ai[5] };
        V3 p2 = { aj[0], aj[1], aj[2] };
        V3 p3 = { aj[3], aj[4], aj[5] };

        // Unnormalized directions (normalization cancels everywhere).
        V3 v0 = vsub(p2, p0);
        V3 v1 = vsub(p2, p1);
        V3 v2 = vsub(p3, p0);
        V3 v3 = vsub(p3, p1);

        // crosses per reference permutation
        V3 c0 = vcross(v0, v1);
        V3 c1 = vcross(v1, v3);
        V3 c2 = vcross(v3, v2);
        V3 c3 = vcross(v2, v0);

        float n0 = vdot(c0, c0);
        float n1 = vdot(c1, c1);
        float n2 = vdot(c2, c2);
        float n3 = vdot(c3, c3);

        float t0 = vdot(c0, c1) * rsqrtf(n0 * n1);
        float t1 = vdot(c1, c2) * rsqrtf(n1 * n2);
        float t2 = vdot(c2, c3) * rsqrtf(n2 * n3);
        float t3 = vdot(c3, c0) * rsqrtf(n3 * n0);

        float omega = fast_asinf(t0) + fast_asinf(t1)
                    + fast_asinf(t2) + fast_asinf(t3);

        // sign(dot(cross(p3-p2, p1-p0), v0)) == sign(dot(c0, v2))
        float sg = vdot(c0, v2);
        float sign = (sg > 0.0f) ? 1.0f : ((sg < 0.0f) ? -1.0f : 0.0f);

        op[(size_t)f * S_PAIRS_C] = omega * sign * 0.15915494309189535f;
    }
}

extern "C" void kernel_launch(void* const* d_in, const int* in_sizes, int n_in,
                              void* d_out, int out_size) {
    const float* xyz = (const float*)d_in[0];
    float* out = (float*)d_out;
    dim3 grid((S_PAIRS_C + BLOCK_T - 1) / BLOCK_T, N_FRAMES_C / F_TILE);
    writhe_kernel<<<grid, BLOCK_T>>>(xyz, out);
}

// round 7
// speedup vs baseline: 1.6995x; 1.0039x over previous
#include <cuda_runtime.h>

// TorchWrithe: writhe of all non-adjacent segment pairs per frame.
// B=128, N=300, SEG_LEN=1 -> S=44253 pairs, out (B,S) f32.
// Segment row s <-> (i, j): i ascending, j in [i+2, 298]; cum(i)=297i - i(i-1)/2.
//
// This version packs TWO frames per thread iteration using Blackwell f32x2
// packed math (fma.rn.f32x2 / mul.rn.f32x2): one issue slot, two fp32 lanes.

#define N_FRAMES_C 128
#define N_ATOMS_C  300
#define S_PAIRS_C  44253
#define BLOCK_T 256
#define F_TILE 8
#define FLOATS_PER_FRAME (N_ATOMS_C * 3)          // 900
#define SLAB_FLOATS (F_TILE * FLOATS_PER_FRAME)   // 7200
#define SLAB_VEC4 (SLAB_FLOATS / 4)               // 1800

__device__ __forceinline__ int fcum(int i) {
    return 297 * i - (i * (i - 1)) / 2;
}

// ---------- packed f32x2 primitives ----------
struct P2 { unsigned long long v; };

__device__ __forceinline__ P2 pk(float lo, float hi) {
    P2 r; asm("mov.b64 %0,{%1,%2};" : "=l"(r.v) : "f"(lo), "f"(hi)); return r;
}
__device__ __forceinline__ void up(P2 p, float& lo, float& hi) {
    asm("mov.b64 {%0,%1},%2;" : "=f"(lo), "=f"(hi) : "l"(p.v));
}
__device__ __forceinline__ P2 fma2(P2 a, P2 b, P2 c) {
    P2 r; asm("fma.rn.f32x2 %0,%1,%2,%3;" : "=l"(r.v) : "l"(a.v), "l"(b.v), "l"(c.v));
    return r;
}
__device__ __forceinline__ P2 mul2(P2 a, P2 b) {
    P2 r; asm("mul.rn.f32x2 %0,%1,%2;" : "=l"(r.v) : "l"(a.v), "l"(b.v));
    return r;
}
__device__ __forceinline__ P2 c2(float x) { return pk(x, x); }

struct V3P { P2 x, y, z; };

__device__ __forceinline__ P2 sub2_(P2 a, P2 b, P2 NEG1) { return fma2(b, NEG1, a); }
__device__ __forceinline__ P2 add2_(P2 a, P2 b, P2 ONE)  { return fma2(a, ONE, b); }

__device__ __forceinline__ V3P vsub2(V3P a, V3P b, P2 NEG1) {
    return { sub2_(a.x, b.x, NEG1), sub2_(a.y, b.y, NEG1), sub2_(a.z, b.z, NEG1) };
}
__device__ __forceinline__ V3P vcross2(V3P a, V3P b, P2 NEG1) {
    V3P r;
    r.x = sub2_(mul2(a.y, b.z), mul2(a.z, b.y), NEG1);
    r.y = sub2_(mul2(a.z, b.x), mul2(a.x, b.z), NEG1);
    r.z = sub2_(mul2(a.x, b.y), mul2(a.y, b.x), NEG1);
    return r;
}
__device__ __forceinline__ P2 vdot2(V3P a, V3P b) {
    return fma2(a.z, b.z, fma2(a.y, b.y, mul2(a.x, b.x)));
}

__device__ __forceinline__ float copysign_bits(float mag, float sgnsrc) {
    return __int_as_float((__float_as_int(mag) & 0x7fffffff)
                        | (__float_as_int(sgnsrc) & 0x80000000u));
}

// Packed asin via A&S 4.4.46: asin(a) = pi/2 - sqrt(1-a) * P7(a), a in [0,1],
// |err| <= 2e-8. Regime-free (no selects). |t| slightly > 1 from rounding
// clamps to exactly +-pi/2 via max(1-a, 0).
__device__ __forceinline__ P2 asin2(P2 t, P2 HALFPI) {
    float tl, th; up(t, tl, th);
    float al = fabsf(tl), ah = fabsf(th);
    float ml = fmaxf(1.0f - al, 0.0f);
    float mh = fmaxf(1.0f - ah, 0.0f);
    float sl = ml * rsqrtf(ml + 1e-30f);      // sqrt(1-a), 0-safe
    float sh = mh * rsqrtf(mh + 1e-30f);
    P2 a = pk(al, ah);
    P2 s = pk(sl, sh);
    // Pneg(a) = -(a0 + a1 a + ... + a7 a^7), Horner with negated coeffs.
    P2 p = c2( 0.0012624911f);
    p = fma2(p, a, c2(-0.0066700901f));
    p = fma2(p, a, c2( 0.0170881256f));
    p = fma2(p, a, c2(-0.0308918810f));
    p = fma2(p, a, c2( 0.0501743046f));
    p = fma2(p, a, c2(-0.0889789874f));
    p = fma2(p, a, c2( 0.2145988016f));
    p = fma2(p, a, c2(-1.5707963050f));
    P2 r = fma2(s, p, HALFPI);                // pi/2 + s*Pneg = pi/2 - s*P
    float rl, rh; up(r, rl, rh);
    return pk(copysign_bits(rl, tl), copysign_bits(rh, th));
}

__global__ __launch_bounds__(BLOCK_T)
void writhe_kernel(const float* __restrict__ xyz, float* __restrict__ out) {
    __shared__ float sm[SLAB_FLOATS];            // 28800 B, linear slab
    const int b0 = blockIdx.y * F_TILE;
    {
        const float4* __restrict__ src4 =
            (const float4*)(xyz + (size_t)b0 * FLOATS_PER_FRAME);
        float4* dst4 = (float4*)sm;
        #pragma unroll
        for (int k = 0; k < 8; ++k) {
            int t = threadIdx.x + k * BLOCK_T;
            if (t < SLAB_VEC4) dst4[t] = src4[t];
        }
    }
    __syncthreads();

    const int s = blockIdx.x * BLOCK_T + threadIdx.x;
    if (s >= S_PAIRS_C) return;

    // Invert s -> (i, j), once per thread.
    float disc = 354025.0f - 8.0f * (float)s;
    int i = (int)((595.0f - sqrtf(disc)) * 0.5f);
    if (i < 0) i = 0;
    if (i > 296) i = 296;
    while (i > 0 && fcum(i) > s) --i;
    while (fcum(i + 1) <= s) ++i;
    const int j = i + 2 + (s - fcum(i));

    const float* __restrict__ bi = sm + 3 * i;   // atoms i, i+1
    const float* __restrict__ bj = sm + 3 * j;   // atoms j, j+1
    float* __restrict__ op = out + (size_t)b0 * S_PAIRS_C + s;

    const P2 ONE    = c2(1.0f);
    const P2 NEG1   = c2(-1.0f);
    const P2 HALFPI = c2(1.5707963267948966f);

    #pragma unroll
    for (int g = 0; g < F_TILE / 2; ++g) {
        const float* aA = bi + (2 * g)     * FLOATS_PER_FRAME;
        const float* aB = bi + (2 * g + 1) * FLOATS_PER_FRAME;
        const float* cA = bj + (2 * g)     * FLOATS_PER_FRAME;
        const float* cB = bj + (2 * g + 1) * FLOATS_PER_FRAME;

        // Pack coordinates: lane-lo = frame 2g, lane-hi = frame 2g+1.
        V3P p0 = { pk(aA[0], aB[0]), pk(aA[1], aB[1]), pk(aA[2], aB[2]) };
        V3P p1 = { pk(aA[3], aB[3]), pk(aA[4], aB[4]), pk(aA[5], aB[5]) };
        V3P p2 = { pk(cA[0], cB[0]), pk(cA[1], cB[1]), pk(cA[2], cB[2]) };
        V3P p3 = { pk(cA[3], cB[3]), pk(cA[4], cB[4]), pk(cA[5], cB[5]) };

        // Unnormalized directions (normalization cancels everywhere).
        V3P v0 = vsub2(p2, p0, NEG1);
        V3P v1 = vsub2(p2, p1, NEG1);
        V3P v2 = vsub2(p3, p0, NEG1);
        V3P v3 = vsub2(p3, p1, NEG1);

        // crosses per reference permutation
        V3P c0 = vcross2(v0, v1, NEG1);
        V3P c1 = vcross2(v1, v3, NEG1);
        V3P c2v = vcross2(v3, v2, NEG1);
        V3P c3 = vcross2(v2, v0, NEG1);

        P2 n0 = vdot2(c0, c0);
        P2 n1 = vdot2(c1, c1);
        P2 n2 = vdot2(c2v, c2v);
        P2 n3 = vdot2(c3, c3);

        // t_ab = dot(ca,cb) * rsqrt(na*nb); rsqrt per-lane (MUFU).
        P2 q01 = mul2(n0, n1);
        P2 q12 = mul2(n1, n2);
        P2 q23 = mul2(n2, n3);
        P2 q30 = mul2(n3, n0);
        float ql, qh;
        up(q01, ql, qh); P2 r01 = pk(rsqrtf(ql), rsqrtf(qh));
        up(q12, ql, qh); P2 r12 = pk(rsqrtf(ql), rsqrtf(qh));
        up(q23, ql, qh); P2 r23 = pk(rsqrtf(ql), rsqrtf(qh));
        up(q30, ql, qh); P2 r30 = pk(rsqrtf(ql), rsqrtf(qh));

        P2 t0 = mul2(vdot2(c0, c1),  r01);
        P2 t1 = mul2(vdot2(c1, c2v), r12);
        P2 t2 = mul2(vdot2(c2v, c3), r23);
        P2 t3 = mul2(vdot2(c3, c0),  r30);

        P2 omega = add2_(add2_(asin2(t0, HALFPI), asin2(t1, HALFPI), ONE),
                         add2_(asin2(t2, HALFPI), asin2(t3, HALFPI), ONE), ONE);

        // sign(dot(cross(p3-p2, p1-p0), v0)) == sign(dot(c0, v2)); fold 1/(2pi).
        P2 sg = vdot2(c0, v2);
        float sgl, sgh; up(sg, sgl, sgh);
        const float K = 0.15915494309189535f;
        float gl = (sgl > 0.0f) ? K : ((sgl < 0.0f) ? -K : 0.0f);
        float gh = (sgh > 0.0f) ? K : ((sgh < 0.0f) ? -K : 0.0f);
        P2 res = mul2(omega, pk(gl, gh));

        float rl, rh; up(res, rl, rh);
        op[(size_t)(2 * g)     * S_PAIRS_C] = rl;
        op[(size_t)(2 * g + 1) * S_PAIRS_C] = rh;
    }
}

extern "C" void kernel_launch(void* const* d_in, const int* in_sizes, int n_in,
                              void* d_out, int out_size) {
    const float* xyz = (const float*)d_in[0];
    float* out = (float*)d_out;
    dim3 grid((S_PAIRS_C + BLOCK_T - 1) / BLOCK_T, N_FRAMES_C / F_TILE);
    writhe_kernel<<<grid, BLOCK_T>>>(xyz, out);
}

// round 8
// speedup vs baseline: 1.7918x; 1.0543x over previous
#include <cuda_runtime.h>

// TorchWrithe: writhe of all non-adjacent segment pairs per frame.
// B=128, N=300, SEG_LEN=1 -> S=44253 pairs, out (B,S) f32.
//
// Gram-basis form: w=p1-p0, u=p3-p2, v0=p2-p0. Then
//   c0=-A, c1=B-C, c2=A-C, c3=-B  with A=v0xw, B=v0xu, C=wxu.
// All writhe dot products come from the Gram matrix of {A,B,C}.
// Two frames are packed per f32x2 instruction (Blackwell packed fp32).

#define N_FRAMES_C 128
#define N_ATOMS_C  300
#define S_PAIRS_C  44253
#define BLOCK_T 128
#define F_TILE 8
#define FLOATS_PER_FRAME (N_ATOMS_C * 3)          // 900
#define SLAB_FLOATS (F_TILE * FLOATS_PER_FRAME)   // 7200
#define SLAB_VEC4 (SLAB_FLOATS / 4)               // 1800

__device__ __forceinline__ int fcum(int i) {
    return 297 * i - (i * (i - 1)) / 2;
}

// ---------- packed f32x2 primitives ----------
struct P2 { unsigned long long v; };

__device__ __forceinline__ P2 pk(float lo, float hi) {
    P2 r; asm("mov.b64 %0,{%1,%2};" : "=l"(r.v) : "f"(lo), "f"(hi)); return r;
}
__device__ __forceinline__ void up(P2 p, float& lo, float& hi) {
    asm("mov.b64 {%0,%1},%2;" : "=f"(lo), "=f"(hi) : "l"(p.v));
}
__device__ __forceinline__ P2 fma2(P2 a, P2 b, P2 c) {
    P2 r; asm("fma.rn.f32x2 %0,%1,%2,%3;" : "=l"(r.v) : "l"(a.v), "l"(b.v), "l"(c.v));
    return r;
}
__device__ __forceinline__ P2 mul2(P2 a, P2 b) {
    P2 r; asm("mul.rn.f32x2 %0,%1,%2;" : "=l"(r.v) : "l"(a.v), "l"(b.v));
    return r;
}
__device__ __forceinline__ P2 add2(P2 a, P2 b) {
    P2 r; asm("add.rn.f32x2 %0,%1,%2;" : "=l"(r.v) : "l"(a.v), "l"(b.v));
    return r;
}
__device__ __forceinline__ P2 c2(float x) { return pk(x, x); }

struct V3P { P2 x, y, z; };

__device__ __forceinline__ P2 sub2_(P2 a, P2 b, P2 NEG1) { return fma2(b, NEG1, a); }

__device__ __forceinline__ V3P vsub2(V3P a, V3P b, P2 NEG1) {
    return { sub2_(a.x, b.x, NEG1), sub2_(a.y, b.y, NEG1), sub2_(a.z, b.z, NEG1) };
}
__device__ __forceinline__ V3P vcross2(V3P a, V3P b, P2 NEG1) {
    V3P r;
    r.x = sub2_(mul2(a.y, b.z), mul2(a.z, b.y), NEG1);
    r.y = sub2_(mul2(a.z, b.x), mul2(a.x, b.z), NEG1);
    r.z = sub2_(mul2(a.x, b.y), mul2(a.y, b.x), NEG1);
    return r;
}
__device__ __forceinline__ P2 vdot2(V3P a, V3P b) {
    return fma2(a.z, b.z, fma2(a.y, b.y, mul2(a.x, b.x)));
}

__device__ __forceinline__ float copysign_bits(float mag, float sgnsrc) {
    return __int_as_float((__float_as_int(mag) & 0x7fffffff)
                        | (__float_as_int(sgnsrc) & 0x80000000u));
}

// Packed asin via A&S 4.4.46: asin(a) = pi/2 - sqrt(1-a) * P7(a), a in [0,1],
// |err| <= 2e-8. Regime-free. |t| slightly > 1 clamps to +-pi/2 via max(1-a,0).
__device__ __forceinline__ P2 asin2(P2 t, P2 HALFPI) {
    float tl, th; up(t, tl, th);
    float al = fabsf(tl), ah = fabsf(th);
    float ml = fmaxf(1.0f - al, 0.0f);
    float mh = fmaxf(1.0f - ah, 0.0f);
    float sl = ml * rsqrtf(ml + 1e-30f);      // sqrt(1-a), 0-safe
    float sh = mh * rsqrtf(mh + 1e-30f);
    P2 a = pk(al, ah);
    P2 s = pk(sl, sh);
    P2 p = c2( 0.0012624911f);
    p = fma2(p, a, c2(-0.0066700901f));
    p = fma2(p, a, c2( 0.0170881256f));
    p = fma2(p, a, c2(-0.0308918810f));
    p = fma2(p, a, c2( 0.0501743046f));
    p = fma2(p, a, c2(-0.0889789874f));
    p = fma2(p, a, c2( 0.2145988016f));
    p = fma2(p, a, c2(-1.5707963050f));
    P2 r = fma2(s, p, HALFPI);                // pi/2 - s*P
    float rl, rh; up(r, rl, rh);
    return pk(copysign_bits(rl, tl), copysign_bits(rh, th));
}

__global__ __launch_bounds__(BLOCK_T, 8)
void writhe_kernel(const float* __restrict__ xyz, float* __restrict__ out) {
    __shared__ float sm[SLAB_FLOATS];            // 28800 B, linear slab
    const int b0 = blockIdx.y * F_TILE;
    {
        const float4* __restrict__ src4 =
            (const float4*)(xyz + (size_t)b0 * FLOATS_PER_FRAME);
        float4* dst4 = (float4*)sm;
        #pragma unroll
        for (int k = 0; k < 15; ++k) {
            int t = threadIdx.x + k * BLOCK_T;
            if (t < SLAB_VEC4) dst4[t] = src4[t];
        }
    }
    __syncthreads();

    const int s = blockIdx.x * BLOCK_T + threadIdx.x;
    if (s >= S_PAIRS_C) return;

    // Invert s -> (i, j), once per thread.
    float disc = 354025.0f - 8.0f * (float)s;
    int i = (int)((595.0f - sqrtf(disc)) * 0.5f);
    if (i < 0) i = 0;
    if (i > 296) i = 296;
    while (i > 0 && fcum(i) > s) --i;
    while (fcum(i + 1) <= s) ++i;
    const int j = i + 2 + (s - fcum(i));

    const float* __restrict__ bi = sm + 3 * i;   // atoms i, i+1
    const float* __restrict__ bj = sm + 3 * j;   // atoms j, j+1
    float* __restrict__ op = out + (size_t)b0 * S_PAIRS_C + s;

    const P2 NEG1   = c2(-1.0f);
    const P2 NEG2   = c2(-2.0f);
    const P2 HALFPI = c2(1.5707963267948966f);

    #pragma unroll
    for (int g = 0; g < F_TILE / 2; ++g) {
        const float* aA = bi + (2 * g)     * FLOATS_PER_FRAME;
        const float* aB = bi + (2 * g + 1) * FLOATS_PER_FRAME;
        const float* cA = bj + (2 * g)     * FLOATS_PER_FRAME;
        const float* cB = bj + (2 * g + 1) * FLOATS_PER_FRAME;

        // Pack coordinates: lane-lo = frame 2g, lane-hi = frame 2g+1.
        V3P p0 = { pk(aA[0], aB[0]), pk(aA[1], aB[1]), pk(aA[2], aB[2]) };
        V3P p1 = { pk(aA[3], aB[3]), pk(aA[4], aB[4]), pk(aA[5], aB[5]) };
        V3P p2 = { pk(cA[0], cB[0]), pk(cA[1], cB[1]), pk(cA[2], cB[2]) };
        V3P p3 = { pk(cA[3], cB[3]), pk(cA[4], cB[4]), pk(cA[5], cB[5]) };

        // Gram basis: w = p1-p0, u = p3-p2, v0 = p2-p0.
        V3P w  = vsub2(p1, p0, NEG1);
        V3P u  = vsub2(p3, p2, NEG1);
        V3P v0 = vsub2(p2, p0, NEG1);

        V3P A = vcross2(v0, w, NEG1);
        V3P B = vcross2(v0, u, NEG1);
        V3P C = vcross2(w,  u, NEG1);

        // Gram matrix of {A,B,C} + A.u for the sign.
        P2 aa = vdot2(A, A);
        P2 bb = vdot2(B, B);
        P2 cc = vdot2(C, C);
        P2 ab = vdot2(A, B);
        P2 ac = vdot2(A, C);
        P2 bc = vdot2(B, C);
        P2 au = vdot2(A, u);

        // Norms: n0=|c0|^2=aa, n1=|B-C|^2, n2=|A-C|^2, n3=|c3|^2=bb.
        P2 n1 = fma2(bc, NEG2, add2(bb, cc));
        P2 n2 = fma2(ac, NEG2, add2(aa, cc));

        // Cross-dots: d01=c0.c1=ac-ab, d12=c1.c2=(ab-bc)+(cc-ac),
        //             d23=c2.c3=bc-ab, d30=c3.c0=ab.
        P2 d01 = sub2_(ac, ab, NEG1);
        P2 d12 = add2(sub2_(ab, bc, NEG1), sub2_(cc, ac, NEG1));
        P2 d23 = sub2_(bc, ab, NEG1);

        // t_ab = d_ab * rsqrt(n_a * n_b); rsqrt per-lane (MUFU).
        P2 q01 = mul2(aa, n1);
        P2 q12 = mul2(n1, n2);
        P2 q23 = mul2(n2, bb);
        P2 q30 = mul2(bb, aa);
        float ql, qh;
        up(q01, ql, qh); P2 r01 = pk(rsqrtf(ql), rsqrtf(qh));
        up(q12, ql, qh); P2 r12 = pk(rsqrtf(ql), rsqrtf(qh));
        up(q23, ql, qh); P2 r23 = pk(rsqrtf(ql), rsqrtf(qh));
        up(q30, ql, qh); P2 r30 = pk(rsqrtf(ql), rsqrtf(qh));

        P2 t0 = mul2(d01, r01);
        P2 t1 = mul2(d12, r12);
        P2 t2 = mul2(d23, r23);
        P2 t3 = mul2(ab,  r30);

        P2 omega = add2(add2(asin2(t0, HALFPI), asin2(t1, HALFPI)),
                        add2(asin2(t2, HALFPI), asin2(t3, HALFPI)));

        // sign term: dot(c0, v2) = -A.u  (A is orthogonal to v0). Fold 1/(2pi).
        float sgl, sgh; up(au, sgl, sgh);
        const float K = 0.15915494309189535f;
        float gl = (sgl < 0.0f) ? K : ((sgl > 0.0f) ? -K : 0.0f);
        float gh = (sgh < 0.0f) ? K : ((sgh > 0.0f) ? -K : 0.0f);
        P2 res = mul2(omega, pk(gl, gh));

        float rl, rh; up(res, rl, rh);
        op[(size_t)(2 * g)     * S_PAIRS_C] = rl;
        op[(size_t)(2 * g + 1) * S_PAIRS_C] = rh;
    }
}

extern "C" void kernel_launch(void* const* d_in, const int* in_sizes, int n_in,
                              void* d_out, int out_size) {
    const float* xyz = (const float*)d_in[0];
    float* out = (float*)d_out;
    dim3 grid((S_PAIRS_C + BLOCK_T - 1) / BLOCK_T, N_FRAMES_C / F_TILE);
    writhe_kernel<<<grid, BLOCK_T>>>(xyz, out);
}